// round 17
// baseline (speedup 1.0000x reference)
#include <cuda_runtime.h>
#include <cuda_fp16.h>
#include <cstdint>

#define B      64
#define PP     196
#define ENC    2048
#define LCAP   32
#define V      20000
#define ATT    512
#define EMB    512
#define DEC    512
#define TSTEPS 31
#define XDIM   (EMB+ENC)   /* 2560 */
#define G4     (4*DEC)     /* 2048 */
#define NH     (B*TSTEPS)  /* 1984 */
#define HPN    (ATT+ENC+G4) /* 4608 */
#define HPS    ((size_t)B*HPN)
#define GS     ((size_t)B*G4)

// ---------------- device scratch ----------------
__device__ __half g_att1h[(size_t)B*PP*ATT];
__device__ __half g_ench[(size_t)B*PP*ENC];
__device__ __half g_fcWh[(size_t)V*DEC];
__device__ __half g_Whph[(size_t)HPN*DEC];
__device__ __half g_Wihh[(size_t)G4*ENC];
__device__ __half g_Wihe[(size_t)G4*EMB];
__device__ __half g_Weah[(size_t)ATT*ENC];
__device__ __half g_embh[(size_t)V*EMB];
__device__ __half g_Winih[(size_t)1024*ENC];   // [W_init_h;W_init_c] fp16
__device__ __half g_meanh[B*ENC];              // fp16 mean encoder
__device__ __half g_hh[B*DEC];
__device__ __half g_hhist[(size_t)NH*DEC];
__device__ __half g_xeh[B*ENC];
__device__ float  g_c[B*DEC];
__device__ float  g_hppart[2*HPS];
__device__ float  g_gpart[8*GS];
__device__ float  g_eg[(size_t)NH*G4];
__device__ int    g_bact[TSTEPS];
__device__ int    g_cnt3[TSTEPS];

__device__ __forceinline__ float sigmoidf_(float x){ return 1.0f/(1.0f+expf(-x)); }
__device__ __forceinline__ void mma_f16(float* d, uint32_t a0, uint32_t a1, uint32_t a2, uint32_t a3,
                                        uint32_t b0, uint32_t b1){
  asm volatile("mma.sync.aligned.m16n8k16.row.col.f32.f16.f16.f32 "
    "{%0,%1,%2,%3},{%4,%5,%6,%7},{%8,%9},{%0,%1,%2,%3};"
    : "+f"(d[0]),"+f"(d[1]),"+f"(d[2]),"+f"(d[3])
    : "r"(a0),"r"(a1),"r"(a2),"r"(a3),"r"(b0),"r"(b1));
}

// ---------------- one-time kernels ----------------
__global__ void k_bact(const int* __restrict__ caplen){
  int t = threadIdx.x;
  if (t < TSTEPS){
    int c = 0;
    for (int b=0;b<B;b++) c += ((caplen[b]-1) > t) ? 1 : 0;
    g_bact[t] = c;
  }
}

// fp16 encoder copy + fp16 mean
__global__ void k_cvtmean(const float* __restrict__ enc){
  int b = blockIdx.x;
  int e = blockIdx.y*256 + threadIdx.x;
  const float* p0 = enc + (size_t)b*PP*ENC + e;
  __half* h0 = g_ench + (size_t)b*PP*ENC + e;
  float s = 0.f;
  #pragma unroll 4
  for (int p=0;p<PP;p++){
    float v = p0[(size_t)p*ENC];
    s += v;
    h0[(size_t)p*ENC] = __float2half_rn(v);
  }
  g_meanh[b*ENC + e] = __float2half_rn(s * (1.0f/PP));
}

#define N4_FCW  ((size_t)V*DEC/4)
#define N4_WEAH ((size_t)ATT*ENC/4)
#define N4_EMBH ((size_t)V*EMB/4)
#define N4_HP   ((size_t)HPN*DEC/4)
#define N4_WIH  ((size_t)G4*XDIM/4)
#define N4_WINI ((size_t)1024*ENC/4)
#define N4_ALL  (N4_FCW + N4_WEAH + N4_EMBH + N4_HP + N4_WIH + N4_WINI)
__global__ void k_cvtall(const float* __restrict__ fcW, const float* __restrict__ weah,
                         const float* __restrict__ embt, const float* __restrict__ Wda,
                         const float* __restrict__ Wbeta, const float* __restrict__ Whh,
                         const float* __restrict__ Wih,
                         const float* __restrict__ Winh, const float* __restrict__ Winc){
  size_t i = (size_t)blockIdx.x*blockDim.x + threadIdx.x;
  if (i >= N4_ALL) return;
  float4 v;
  __half2* o;
  if (i < N4_FCW){
    v = ((const float4*)fcW)[i];
    o = (__half2*)(g_fcWh) + i*2;
  } else if (i < N4_FCW + N4_WEAH){
    size_t k = i - N4_FCW;
    v = ((const float4*)weah)[k];
    o = (__half2*)(g_Weah) + k*2;
  } else if (i < N4_FCW + N4_WEAH + N4_EMBH){
    size_t k = i - N4_FCW - N4_WEAH;
    v = ((const float4*)embt)[k];
    o = (__half2*)(g_embh) + k*2;
  } else if (i < N4_FCW + N4_WEAH + N4_EMBH + N4_HP){
    size_t k = i - N4_FCW - N4_WEAH - N4_EMBH;
    size_t el = k*4;
    int row = (int)(el / DEC), col = (int)(el % DEC);
    const float* src;
    if (row < ATT)          src = Wda   + (size_t)row*DEC;
    else if (row < ATT+ENC) src = Wbeta + (size_t)(row-ATT)*DEC;
    else                    src = Whh   + (size_t)(row-ATT-ENC)*DEC;
    v = *(const float4*)(src + col);
    o = (__half2*)(g_Whph + el);
  } else if (i < N4_FCW + N4_WEAH + N4_EMBH + N4_HP + N4_WIH){
    size_t k = i - N4_FCW - N4_WEAH - N4_EMBH - N4_HP;
    size_t el = k*4;
    int row = (int)(el / XDIM), col = (int)(el % XDIM);
    v = *(const float4*)(Wih + el);
    if (col < EMB) o = (__half2*)(g_Wihe + (size_t)row*EMB + col);
    else           o = (__half2*)(g_Wihh + (size_t)row*ENC + (col-EMB));
  } else {
    size_t k = i - N4_FCW - N4_WEAH - N4_EMBH - N4_HP - N4_WIH;
    size_t el = k*4;
    int row = (int)(el / ENC), col = (int)(el % ENC);
    const float* src = (row < DEC) ? (Winh + (size_t)row*ENC) : (Winc + (size_t)(row-DEC)*ENC);
    v = *(const float4*)(src + col);
    o = (__half2*)(g_Winih + el);
  }
  o[0] = __floats2half2_rn(v.x, v.y);
  o[1] = __floats2half2_rn(v.z, v.w);
}

// ---------------- fp16 mma core, double-buffered (M=64, BN=128) ----------------
template<int KLEN>
__device__ __forceinline__ void tc16_core(__half2* sbuf,
    const __half* Ap, const __half* Wp0, const __half* Wp1, float acc[8][4]){
  __half2* sA0 = sbuf;
  __half2* sW0 = sbuf + 2*64*20;
  const int AS = 64*20, WS = 128*20;
  int tid=threadIdx.x, lane=tid&31, wp=tid>>5;
  int mr=wp>>1, nc=wp&1;
  int lr=tid>>2, kq8=(tid&3)*8;
  int r = mr*16 + (lane>>2);
  int cq = lane&3;
  uint4 a  = *(const uint4*)(Ap + kq8);
  uint4 w0 = *(const uint4*)(Wp0 + kq8);
  uint4 w1 = *(const uint4*)(Wp1 + kq8);
  *(uint4*)(sA0 + lr*20 + kq8/2)      = a;
  *(uint4*)(sW0 + lr*20 + kq8/2)      = w0;
  *(uint4*)(sW0 + (lr+64)*20 + kq8/2) = w1;
  __syncthreads();
  for (int k0=0;k0<KLEN;k0+=32){
    int cur = (k0>>5)&1;
    __half2* cA = sA0 + cur*AS;
    __half2* cW = sW0 + cur*WS;
    if (k0+32<KLEN){
      a  = *(const uint4*)(Ap + k0+32 + kq8);
      w0 = *(const uint4*)(Wp0 + k0+32 + kq8);
      w1 = *(const uint4*)(Wp1 + k0+32 + kq8);
      __half2* nA = sA0 + (cur^1)*AS;
      __half2* nW = sW0 + (cur^1)*WS;
      *(uint4*)(nA + lr*20 + kq8/2)      = a;
      *(uint4*)(nW + lr*20 + kq8/2)      = w0;
      *(uint4*)(nW + (lr+64)*20 + kq8/2) = w1;
    }
    #pragma unroll
    for (int kk=0;kk<2;kk++){
      int o = kk*8 + cq;
      uint32_t a0=*(uint32_t*)(cA + r*20 + o);
      uint32_t a1=*(uint32_t*)(cA + (r+8)*20 + o);
      uint32_t a2=*(uint32_t*)(cA + r*20 + o+4);
      uint32_t a3=*(uint32_t*)(cA + (r+8)*20 + o+4);
      #pragma unroll
      for (int j=0;j<8;j++){
        int n = nc*64 + j*8 + (lane>>2);
        uint32_t b0=*(uint32_t*)(cW + n*20 + o);
        uint32_t b1=*(uint32_t*)(cW + n*20 + o+4);
        mma_f16(acc[j], a0, a1, a2, a3, b0, b1);
      }
    }
    __syncthreads();
  }
}

// ---------------- fp16 mma core, BM=128 x BN=64 (fcall) ----------------
template<int KLEN>
__device__ __forceinline__ void tc16m128_core(__half2* sbuf,
    const __half* Ap0, const __half* Ap1, const __half* Wp, float acc[8][4]){
  __half2* sA0 = sbuf;
  __half2* sW0 = sbuf + 2*128*20;
  const int AS = 128*20, WS = 64*20;
  int tid=threadIdx.x, lane=tid&31, wp=tid>>5;
  int lr=tid>>2, kq8=(tid&3)*8;
  int r = wp*16 + (lane>>2);
  int cq = lane&3;
  uint4 a0v = *(const uint4*)(Ap0 + kq8);
  uint4 a1v = *(const uint4*)(Ap1 + kq8);
  uint4 w0  = *(const uint4*)(Wp + kq8);
  *(uint4*)(sA0 + lr*20 + kq8/2)        = a0v;
  *(uint4*)(sA0 + (lr+64)*20 + kq8/2)   = a1v;
  *(uint4*)(sW0 + lr*20 + kq8/2)        = w0;
  __syncthreads();
  for (int k0=0;k0<KLEN;k0+=32){
    int cur = (k0>>5)&1;
    __half2* cA = sA0 + cur*AS;
    __half2* cW = sW0 + cur*WS;
    if (k0+32<KLEN){
      a0v = *(const uint4*)(Ap0 + k0+32 + kq8);
      a1v = *(const uint4*)(Ap1 + k0+32 + kq8);
      w0  = *(const uint4*)(Wp + k0+32 + kq8);
      __half2* nA = sA0 + (cur^1)*AS;
      __half2* nW = sW0 + (cur^1)*WS;
      *(uint4*)(nA + lr*20 + kq8/2)      = a0v;
      *(uint4*)(nA + (lr+64)*20 + kq8/2) = a1v;
      *(uint4*)(nW + lr*20 + kq8/2)      = w0;
    }
    #pragma unroll
    for (int kk=0;kk<2;kk++){
      int o = kk*8 + cq;
      uint32_t a0=*(uint32_t*)(cA + r*20 + o);
      uint32_t a1=*(uint32_t*)(cA + (r+8)*20 + o);
      uint32_t a2=*(uint32_t*)(cA + r*20 + o+4);
      uint32_t a3=*(uint32_t*)(cA + (r+8)*20 + o+4);
      #pragma unroll
      for (int j=0;j<8;j++){
        int n = j*8 + (lane>>2);
        uint32_t b0=*(uint32_t*)(cW + n*20 + o);
        uint32_t b1=*(uint32_t*)(cW + n*20 + o+4);
        mma_f16(acc[j], a0, a1, a2, a3, b0, b1);
      }
    }
    __syncthreads();
  }
}
#define SBUF_H2 (2*(64*20 + 128*20))
#define ACC_INIT(acc) { _Pragma("unroll") for (int j=0;j<8;j++){ acc[j][0]=acc[j][1]=acc[j][2]=acc[j][3]=0.f; } }

// one-time merged prologue GEMMs:
//   blocks [0,784)    : att1
//   blocks [784,1280) : embgate
//   blocks [1280,1288): h0/c0 init (mean @ [W_init_h;W_init_c]^T, K=2048)
__global__ void __launch_bounds__(256) k_pro(const float* __restrict__ bias,
                                             const int* __restrict__ caps,
                                             const float* __restrict__ bh,
                                             const float* __restrict__ bc){
  __shared__ __align__(16) __half2 sbuf[SBUF_H2];
  int i = blockIdx.x;
  int tid=threadIdx.x, lane=tid&31, wp=tid>>5;
  int mr=wp>>1, nc=wp&1, lr=tid>>2;
  float acc[8][4]; ACC_INIT(acc)
  if (i < 784){
    int m0 = (i>>2)*64, gn0 = (i&3)*128;
    tc16_core<ENC>(sbuf,
                   g_ench + (size_t)(m0+lr)*ENC,
                   g_Weah + (size_t)(gn0+lr)*ENC,
                   g_Weah + (size_t)(gn0+lr+64)*ENC, acc);
    int r0=m0+mr*16+(lane>>2), c0=(lane&3)*2;
    #pragma unroll
    for (int j=0;j<8;j++){
      int gn=gn0+nc*64+j*8+c0;
      *(__half2*)(g_att1h + (size_t)r0*ATT + gn)     = __floats2half2_rn(acc[j][0]+bias[gn], acc[j][1]+bias[gn+1]);
      *(__half2*)(g_att1h + (size_t)(r0+8)*ATT + gn) = __floats2half2_rn(acc[j][2]+bias[gn], acc[j][3]+bias[gn+1]);
    }
  } else if (i < 1280){
    int k = i - 784;
    int m0 = (k>>4)*64, gn0 = (k&15)*128;
    int gr = m0 + lr;
    int tok = caps[(gr/TSTEPS)*LCAP + (gr%TSTEPS)];
    tc16_core<EMB>(sbuf,
                   g_embh + (size_t)tok*EMB,
                   g_Wihe + (size_t)(gn0+lr)*EMB,
                   g_Wihe + (size_t)(gn0+lr+64)*EMB, acc);
    int r0=m0+mr*16+(lane>>2), c0=(lane&3)*2;
    #pragma unroll
    for (int j=0;j<8;j++){
      int gn=gn0+nc*64+j*8+c0;
      g_eg[(size_t)r0*G4 + gn]       = acc[j][0];
      g_eg[(size_t)r0*G4 + gn+1]     = acc[j][1];
      g_eg[(size_t)(r0+8)*G4 + gn]   = acc[j][2];
      g_eg[(size_t)(r0+8)*G4 + gn+1] = acc[j][3];
    }
  } else {
    int k = i - 1280;
    int gn0 = k*128;
    tc16_core<ENC>(sbuf,
                   g_meanh + lr*ENC,
                   g_Winih + (size_t)(gn0+lr)*ENC,
                   g_Winih + (size_t)(gn0+lr+64)*ENC, acc);
    int r0=mr*16+(lane>>2), c0=(lane&3)*2;
    #pragma unroll
    for (int j=0;j<8;j++){
      int gn=gn0+nc*64+j*8+c0;
      #pragma unroll
      for (int q=0;q<2;q++){
        int rr = r0 + q*8;
        float v0 = acc[j][q*2], v1 = acc[j][q*2+1];
        if (gn < DEC){
          g_hh[rr*DEC + gn]   = __float2half_rn(v0 + bh[gn]);
          g_hh[rr*DEC + gn+1] = __float2half_rn(v1 + bh[gn+1]);
        } else {
          g_c[rr*DEC + gn-DEC]   = v0 + bc[gn-DEC];
          g_c[rr*DEC + gn+1-DEC] = v1 + bc[gn+1-DEC];
        }
      }
    }
  }
}

// ---------------- per-step kernels ----------------
__global__ void __launch_bounds__(256) k_ph1(int t){
  if (blockIdx.x == 0 && threadIdx.x == 0) g_cnt3[t] = 0;
  __shared__ __align__(16) __half2 sbuf[SBUF_H2];
  int tile = blockIdx.x;
  int nt = tile % 36, ks = tile / 36;
  int gn0 = nt*128, kofs = ks*256;
  int tid=threadIdx.x, lane=tid&31, wp=tid>>5;
  int mr=wp>>1, nc=wp&1, lr=tid>>2;
  float acc[8][4]; ACC_INIT(acc)
  tc16_core<256>(sbuf,
                 g_hh + lr*DEC + kofs,
                 g_Whph + (size_t)(gn0+lr)*DEC + kofs,
                 g_Whph + (size_t)(gn0+lr+64)*DEC + kofs, acc);
  int r0=mr*16+(lane>>2), c0=(lane&3)*2;
  float* out = g_hppart + (size_t)ks*HPS;
  #pragma unroll
  for (int j=0;j<8;j++){
    int gn=gn0+nc*64+j*8+c0;
    out[(size_t)r0*HPN + gn]       = acc[j][0];
    out[(size_t)r0*HPN + gn+1]     = acc[j][1];
    out[(size_t)(r0+8)*HPN + gn]   = acc[j][2];
    out[(size_t)(r0+8)*HPN + gn+1] = acc[j][3];
  }
}

// ph2: alpha+awe, one 512-thread block per batch
__global__ void __launch_bounds__(512) k_ph2(
    const float* __restrict__ b_dec_att, const float* __restrict__ w_full,
    const float* __restrict__ b_full, const float* __restrict__ b_beta,
    float* __restrict__ alphas, int t){
  int b = blockIdx.x, tid = threadIdx.x;
  int nact = g_bact[t];
  if (b >= nact){
    for (int p=tid;p<PP;p+=512) alphas[(size_t)b*TSTEPS*PP + (size_t)t*PP + p] = 0.f;
    return;
  }
  __shared__ float s_a2[ATT];
  __shared__ float s_wf[ATT];
  __shared__ float s_e[200];
  __shared__ float s_red[16];
  const float* hp0 = g_hppart + (size_t)b*HPN;
  const float* hp1 = g_hppart + HPS + (size_t)b*HPN;
  for (int a=tid;a<ATT;a+=512){
    s_a2[a] = hp0[a] + hp1[a] + b_dec_att[a];
    s_wf[a] = w_full[a];
  }
  __syncthreads();
  int warp = tid>>5, lane = tid&31;
  float bf = b_full[0];
  for (int p=warp; p<PP; p+=16){
    const __half2* r = (const __half2*)(g_att1h + (size_t)(b*PP+p)*ATT);
    float s=0.f;
    #pragma unroll
    for (int i=0;i<8;i++){
      int a2i = lane + i*32;
      float2 f = __half22float2(r[a2i]);
      int a = a2i*2;
      s += fmaxf(f.x + s_a2[a],0.f)*s_wf[a] + fmaxf(f.y + s_a2[a+1],0.f)*s_wf[a+1];
    }
    #pragma unroll
    for (int o=16;o;o>>=1) s += __shfl_xor_sync(0xffffffffu,s,o);
    if (lane==0) s_e[p] = s + bf;
  }
  __syncthreads();
  float m = (tid < PP) ? s_e[tid] : -1e30f;
  #pragma unroll
  for (int o=16;o;o>>=1) m = fmaxf(m,__shfl_xor_sync(0xffffffffu,m,o));
  if (lane==0) s_red[warp]=m;
  __syncthreads();
  float mx = s_red[0];
  #pragma unroll
  for (int i=1;i<16;i++) mx = fmaxf(mx, s_red[i]);
  __syncthreads();
  float sum = 0.f;
  if (tid < PP){ float ex = expf(s_e[tid]-mx); s_e[tid]=ex; sum=ex; }
  #pragma unroll
  for (int o=16;o;o>>=1) sum += __shfl_xor_sync(0xffffffffu,sum,o);
  if (lane==0) s_red[warp]=sum;
  __syncthreads();
  float tot = 0.f;
  #pragma unroll
  for (int i=0;i<16;i++) tot += s_red[i];
  float inv = 1.0f/tot;
  if (tid < PP){
    float al = s_e[tid]*inv;
    s_e[tid] = al;
    alphas[(size_t)b*TSTEPS*PP + (size_t)t*PP + tid] = al;
  }
  __syncthreads();
  const __half2* eb = (const __half2*)g_ench + (size_t)b*PP*(ENC/2);
  int c0 = tid, c1 = tid + 512;
  float ax=0.f, ay=0.f, cx=0.f, cy=0.f;
  #pragma unroll 2
  for (int p=0;p<PP;p++){
    float al = s_e[p];
    float2 f0 = __half22float2(eb[(size_t)p*(ENC/2) + c0]);
    float2 f1 = __half22float2(eb[(size_t)p*(ENC/2) + c1]);
    ax += al*f0.x; ay += al*f0.y;
    cx += al*f1.x; cy += al*f1.y;
  }
  int e = c0*2;
  float g0 = sigmoidf_(hp0[ATT+e]   + hp1[ATT+e]   + b_beta[e]);
  float g1 = sigmoidf_(hp0[ATT+e+1] + hp1[ATT+e+1] + b_beta[e+1]);
  *(__half2*)(g_xeh + (size_t)b*ENC + e) = __floats2half2_rn(g0*ax, g1*ay);
  int e2 = c1*2;
  float g2 = sigmoidf_(hp0[ATT+e2]   + hp1[ATT+e2]   + b_beta[e2]);
  float g3 = sigmoidf_(hp0[ATT+e2+1] + hp1[ATT+e2+1] + b_beta[e2+1]);
  *(__half2*)(g_xeh + (size_t)b*ENC + e2) = __floats2half2_rn(g2*cx, g3*cy);
}

// ph3: gates split-K8 (128 tiles) + in-kernel barrier + fused lstm
__global__ void __launch_bounds__(256) k_ph3(const float* __restrict__ b_ih,
                                             const float* __restrict__ b_hh, int t){
  __shared__ __align__(16) __half2 sbuf[SBUF_H2];
  int tile = blockIdx.x;
  int nt = tile & 15, ks = tile >> 4;
  int gn0 = nt*128, kofs = ks*256;
  int tid=threadIdx.x, lane=tid&31, wp=tid>>5;
  int mr=wp>>1, nc=wp&1, lr=tid>>2;
  float acc[8][4]; ACC_INIT(acc)
  tc16_core<256>(sbuf,
                 g_xeh + (size_t)lr*ENC + kofs,
                 g_Wihh + (size_t)(gn0+lr)*ENC + kofs,
                 g_Wihh + (size_t)(gn0+lr+64)*ENC + kofs, acc);
  int r0=mr*16+(lane>>2), c0=(lane&3)*2;
  float* out = g_gpart + (size_t)ks*GS;
  #pragma unroll
  for (int j=0;j<8;j++){
    int gn=gn0+nc*64+j*8+c0;
    out[(size_t)r0*G4 + gn]       = acc[j][0];
    out[(size_t)r0*G4 + gn+1]     = acc[j][1];
    out[(size_t)(r0+8)*G4 + gn]   = acc[j][2];
    out[(size_t)(r0+8)*G4 + gn+1] = acc[j][3];
  }
  __syncthreads();
  if (tid == 0){
    __threadfence();
    atomicAdd(&g_cnt3[t], 1);
    while (*(volatile int*)&g_cnt3[t] < 128) __nanosleep(32);
  }
  __syncthreads();
  __threadfence();
  int idx = tile*256 + tid;
  int b = idx >> 9, j = idx & 511;
  if (b >= g_bact[t]) return;
  const float* eg  = g_eg + ((size_t)b*TSTEPS + t)*G4;
  const float* hp0 = g_hppart + (size_t)b*HPN + ATT + ENC;
  const float* hp1 = g_hppart + HPS + (size_t)b*HPN + ATT + ENC;
  float g[4];
  #pragma unroll
  for (int q=0;q<4;q++){
    int off = q*DEC + j;
    float v = eg[off] + b_ih[off] + b_hh[off] + hp0[off] + hp1[off];
    #pragma unroll
    for (int s=0;s<8;s++) v += g_gpart[(size_t)s*GS + (size_t)b*G4 + off];
    g[q] = v;
  }
  float cn = sigmoidf_(g[1])*g_c[b*DEC+j] + sigmoidf_(g[0])*tanhf(g[2]);
  float hn = sigmoidf_(g[3])*tanhf(cn);
  g_c[b*DEC+j]=cn;
  __half hh = __float2half_rn(hn);
  g_hh[b*DEC+j] = hh;
  g_hhist[((size_t)b*TSTEPS + t)*DEC + j] = hh;
}

// deferred batched fc: BM=128 x BN=64. grid (313, 16)
__global__ void __launch_bounds__(256) k_fcall(const float* __restrict__ bias,
                                               float* __restrict__ preds){
  __shared__ __align__(16) __half2 sbuf[SBUF_H2];
  int m0 = blockIdx.y*128, gn0 = blockIdx.x*64;
  int tid=threadIdx.x, lane=tid&31, wp=tid>>5;
  int lr=tid>>2;
  int rA0 = m0 + lr;            if (rA0 >= NH) rA0 = NH-1;
  int rA1 = m0 + lr + 64;       if (rA1 >= NH) rA1 = NH-1;
  int wn  = gn0 + lr;           if (wn  >= V)  wn  = V-1;
  float acc[8][4]; ACC_INIT(acc)
  tc16m128_core<DEC>(sbuf,
                     g_hhist + (size_t)rA0*DEC,
                     g_hhist + (size_t)rA1*DEC,
                     g_fcWh + (size_t)wn*DEC, acc);
  int r0 = m0 + wp*16 + (lane>>2);
  int r1 = r0 + 8;
  int c0 = (lane&3)*2;
  bool v0 = (r0 < NH), v1 = (r1 < NH);
  bool a0 = v0 && ((r0 / TSTEPS) < g_bact[r0 % TSTEPS]);
  bool a1 = v1 && ((r1 / TSTEPS) < g_bact[r1 % TSTEPS]);
  float* row0 = preds + (size_t)r0*V;
  float* row1 = preds + (size_t)r1*V;
  #pragma unroll
  for (int j=0;j<8;j++){
    int gn=gn0+j*8+c0;
    if (gn < V){
      if (v0) row0[gn] = a0 ? (acc[j][0]+bias[gn]) : 0.f;
      if (v1) row1[gn] = a1 ? (acc[j][2]+bias[gn]) : 0.f;
    }
    if (gn+1 < V){
      if (v0) row0[gn+1] = a0 ? (acc[j][1]+bias[gn+1]) : 0.f;
      if (v1) row1[gn+1] = a1 ? (acc[j][3]+bias[gn+1]) : 0.f;
    }
  }
}

// ---------------- launch ----------------
extern "C" void kernel_launch(void* const* d_in, const int* in_sizes, int n_in,
                              void* d_out, int out_size){
  (void)in_sizes; (void)n_in; (void)out_size;
  const float* enc       = (const float*)d_in[0];
  const int*   caps      = (const int*)  d_in[1];
  const int*   caplen    = (const int*)  d_in[2];
  const float* emb_table = (const float*)d_in[3];
  const float* W_enc_att = (const float*)d_in[4];
  const float* b_enc_att = (const float*)d_in[5];
  const float* W_dec_att = (const float*)d_in[6];
  const float* b_dec_att = (const float*)d_in[7];
  const float* w_full    = (const float*)d_in[8];
  const float* b_full    = (const float*)d_in[9];
  const float* W_init_h  = (const float*)d_in[10];
  const float* b_init_h  = (const float*)d_in[11];
  const float* W_init_c  = (const float*)d_in[12];
  const float* b_init_c  = (const float*)d_in[13];
  const float* W_beta    = (const float*)d_in[14];
  const float* b_beta    = (const float*)d_in[15];
  const float* W_ih      = (const float*)d_in[16];
  const float* b_ih      = (const float*)d_in[17];
  const float* W_hh      = (const float*)d_in[18];
  const float* b_hh      = (const float*)d_in[19];
  const float* fc_W      = (const float*)d_in[20];
  const float* fc_b      = (const float*)d_in[21];

  float* preds  = (float*)d_out;                       // [B, T, V]
  float* alphas = preds + (size_t)B*TSTEPS*V;          // [B, T, P]

  k_bact<<<1, 32>>>(caplen);
  k_cvtmean<<<dim3(B, ENC/256), 256>>>(enc);
  k_cvtall<<<(int)((N4_ALL + 255)/256), 256>>>(fc_W, W_enc_att, emb_table,
                                               W_dec_att, W_beta, W_hh, W_ih,
                                               W_init_h, W_init_c);
  k_pro<<<1288, 256>>>(b_enc_att, caps, b_init_h, b_init_c);

  for (int t=0; t<TSTEPS; t++){
    k_ph1<<<72, 256>>>(t);
    k_ph2<<<B, 512>>>(b_dec_att, w_full, b_full, b_beta, alphas, t);
    k_ph3<<<128, 256>>>(b_ih, b_hh, t);
  }
  k_fcall<<<dim3((V+63)/64, (NH+127)/128), 256>>>(fc_b, preds);
}